// round 1
// baseline (speedup 1.0000x reference)
#include <cuda_runtime.h>
#include <math.h>

// Problem constants
#define BATCH 4
#define SEQ   2048
#define DMODEL 512
#define NHEAD 8
#define DHEAD 64
#define DFF   2048
#define MROWS (BATCH * SEQ)   // 8192

// ---------------------------------------------------------------------------
// Scratch (allocation-free: __device__ globals)
// ---------------------------------------------------------------------------
__device__ float g_h  [(size_t)MROWS * DMODEL];
__device__ float g_q  [(size_t)MROWS * DMODEL];
__device__ float g_k  [(size_t)MROWS * DMODEL];
__device__ float g_v  [(size_t)MROWS * DMODEL];
__device__ float g_att[(size_t)MROWS * DMODEL];
__device__ float g_x1 [(size_t)MROWS * DMODEL];
__device__ float g_x2 [(size_t)MROWS * DMODEL];
__device__ float g_ff [(size_t)MROWS * DFF];

// ---------------------------------------------------------------------------
// LayerNorm: gamma*(x-mean)/(std+eps)+beta, std unbiased (ddof=1), eps OUTSIDE
// sqrt. One block (128 threads) per row of 512.
// ---------------------------------------------------------------------------
__global__ void ln_kernel(const float* __restrict__ x,
                          const float* __restrict__ g,
                          const float* __restrict__ b,
                          float* __restrict__ out)
{
    int row = blockIdx.x;
    int t = threadIdx.x;  // 0..127
    const float4 v = ((const float4*)(x + (size_t)row * DMODEL))[t];

    __shared__ float red1[4], red2[4];

    float s = v.x + v.y + v.z + v.w;
    #pragma unroll
    for (int o = 16; o; o >>= 1) s += __shfl_xor_sync(0xffffffffu, s, o);
    if ((t & 31) == 0) red1[t >> 5] = s;
    __syncthreads();
    float mean = (red1[0] + red1[1] + red1[2] + red1[3]) * (1.0f / DMODEL);

    float d0 = v.x - mean, d1 = v.y - mean, d2 = v.z - mean, d3 = v.w - mean;
    float sq = d0*d0 + d1*d1 + d2*d2 + d3*d3;
    #pragma unroll
    for (int o = 16; o; o >>= 1) sq += __shfl_xor_sync(0xffffffffu, sq, o);
    if ((t & 31) == 0) red2[t >> 5] = sq;
    __syncthreads();
    float var = (red2[0] + red2[1] + red2[2] + red2[3]) * (1.0f / (DMODEL - 1));
    float rstd = 1.0f / (sqrtf(var) + 1e-6f);

    const float4 gv = ((const float4*)g)[t];
    const float4 bv = ((const float4*)b)[t];
    float4 o4;
    o4.x = gv.x * d0 * rstd + bv.x;
    o4.y = gv.y * d1 * rstd + bv.y;
    o4.z = gv.z * d2 * rstd + bv.z;
    o4.w = gv.w * d3 * rstd + bv.w;
    ((float4*)(out + (size_t)row * DMODEL))[t] = o4;
}

// ---------------------------------------------------------------------------
// SGEMM: C[M,N] = A[M,K] @ W[K,N] (+bias) (+residual) (+relu)
// Block tile 128x64, BK=16, 256 threads, 8x4 per thread.
// M%128==0, N%64==0, K%16==0 guaranteed by shapes.
// ---------------------------------------------------------------------------
template<bool BIAS, bool RES, bool RELU>
__global__ void __launch_bounds__(256)
gemm_kernel(const float* __restrict__ A, const float* __restrict__ W,
            const float* __restrict__ bias, const float* __restrict__ res,
            float* __restrict__ C, int M, int N, int K)
{
    __shared__ float As[16 * 128];   // transposed: As[k][m]
    __shared__ float Bs[16 * 64];    // Bs[k][n]

    const int tid = threadIdx.x;
    const int tx = tid & 15;         // n dir (x4)
    const int ty = tid >> 4;         // m dir (x8)
    const int m0 = blockIdx.y * 128;
    const int n0 = blockIdx.x * 64;

    float acc[8][4];
    #pragma unroll
    for (int i = 0; i < 8; i++)
        #pragma unroll
        for (int j = 0; j < 4; j++) acc[i][j] = 0.f;

    for (int k0 = 0; k0 < K; k0 += 16) {
        // A tile: 128 rows x 16 cols = 512 float4, 2 per thread, store transposed
        #pragma unroll
        for (int i = 0; i < 2; i++) {
            int vI = tid * 2 + i;
            int row = vI >> 2, cv = vI & 3;
            float4 a = *(const float4*)(A + (size_t)(m0 + row) * K + k0 + cv * 4);
            As[(cv * 4 + 0) * 128 + row] = a.x;
            As[(cv * 4 + 1) * 128 + row] = a.y;
            As[(cv * 4 + 2) * 128 + row] = a.z;
            As[(cv * 4 + 3) * 128 + row] = a.w;
        }
        // B tile: 16 rows x 64 cols = 256 float4, 1 per thread
        {
            int row = tid >> 4, cv = tid & 15;
            *(float4*)(Bs + row * 64 + cv * 4) =
                *(const float4*)(W + (size_t)(k0 + row) * N + n0 + cv * 4);
        }
        __syncthreads();

        #pragma unroll
        for (int k = 0; k < 16; k++) {
            float4 a0 = *(const float4*)(As + k * 128 + ty * 8);
            float4 a1 = *(const float4*)(As + k * 128 + ty * 8 + 4);
            float4 b0 = *(const float4*)(Bs + k * 64 + tx * 4);
            float ar[8] = {a0.x, a0.y, a0.z, a0.w, a1.x, a1.y, a1.z, a1.w};
            float br[4] = {b0.x, b0.y, b0.z, b0.w};
            #pragma unroll
            for (int i = 0; i < 8; i++)
                #pragma unroll
                for (int j = 0; j < 4; j++)
                    acc[i][j] += ar[i] * br[j];
        }
        __syncthreads();
    }

    // Epilogue
    float4 bv = make_float4(0.f, 0.f, 0.f, 0.f);
    if (BIAS) bv = *(const float4*)(bias + n0 + tx * 4);
    #pragma unroll
    for (int i = 0; i < 8; i++) {
        size_t idx = (size_t)(m0 + ty * 8 + i) * N + n0 + tx * 4;
        float4 c = make_float4(acc[i][0], acc[i][1], acc[i][2], acc[i][3]);
        if (BIAS) { c.x += bv.x; c.y += bv.y; c.z += bv.z; c.w += bv.w; }
        if (RES) {
            float4 r = *(const float4*)(res + idx);
            c.x += r.x; c.y += r.y; c.z += r.z; c.w += r.w;
        }
        if (RELU) {
            c.x = fmaxf(c.x, 0.f); c.y = fmaxf(c.y, 0.f);
            c.z = fmaxf(c.z, 0.f); c.w = fmaxf(c.w, 0.f);
        }
        *(float4*)(C + idx) = c;
    }
}

// ---------------------------------------------------------------------------
// Fused attention (flash style), fp32. Q,K,V,O layout: [B, S, H*DHEAD] with
// head h at columns [h*64, h*64+64). Block: 64 queries x full dk=64, iterates
// 64-key tiles with online softmax. CAUSAL skips fully-masked tiles.
// Grid: (S/64, H, B), 256 threads (16x16), 4x4 micro-tile.
// ---------------------------------------------------------------------------
#define ATT_LD 68   // padded row length (floats), keeps 16B alignment

template<bool CAUSAL>
__global__ void __launch_bounds__(256)
attn_kernel(const float* __restrict__ Q, const float* __restrict__ K,
            const float* __restrict__ V, float* __restrict__ O)
{
    extern __shared__ float sm[];
    float* Qs  = sm;                    // [d][q]  64 x ATT_LD
    float* KVs = Qs + 64 * ATT_LD;      // K phase: [d][j]; V phase: [j][d]
    float* Ps  = KVs + 64 * ATT_LD;     // [j][q]
    float* mrow = Ps + 64 * ATT_LD;     // [64]
    float* lrow = mrow + 64;            // [64]
    float* arow = lrow + 64;            // [64]

    const int tid = threadIdx.x;
    const int tx = tid & 15;            // key / out-dim dir (x4)
    const int ty = tid >> 4;            // query dir (x4)
    const int q0 = blockIdx.x * 64;
    const int h  = blockIdx.y;
    const int b  = blockIdx.z;

    const size_t bq = ((size_t)b * SEQ + q0) * DMODEL + (size_t)h * DHEAD;
    const size_t bk = ((size_t)b * SEQ) * DMODEL + (size_t)h * DHEAD;

    if (tid < 64) { mrow[tid] = -INFINITY; lrow[tid] = 0.f; }

    // Load Q tile transposed [d][q]
    for (int idx = tid; idx < 64 * 64; idx += 256) {
        int qq = idx >> 6, d = idx & 63;
        Qs[d * ATT_LD + qq] = Q[bq + (size_t)qq * DMODEL + d];
    }

    float o[4][4];
    #pragma unroll
    for (int i = 0; i < 4; i++)
        #pragma unroll
        for (int j = 0; j < 4; j++) o[i][j] = 0.f;

    const int ntiles = CAUSAL ? (blockIdx.x + 1) : (SEQ / 64);

    for (int t = 0; t < ntiles; t++) {
        const int j0 = t * 64;
        // Load K tile transposed [d][j]
        for (int idx = tid; idx < 64 * 64; idx += 256) {
            int jj = idx >> 6, d = idx & 63;
            KVs[d * ATT_LD + jj] = K[bk + (size_t)(j0 + jj) * DMODEL + d];
        }
        __syncthreads();

        // Scores: s[qi][jj] = sum_d Q[q][d] * K[j][d]
        float s[4][4];
        #pragma unroll
        for (int i = 0; i < 4; i++)
            #pragma unroll
            for (int j = 0; j < 4; j++) s[i][j] = 0.f;

        #pragma unroll 8
        for (int d = 0; d < 64; d++) {
            float4 qv = *(const float4*)(Qs + d * ATT_LD + ty * 4);
            float4 kv = *(const float4*)(KVs + d * ATT_LD + tx * 4);
            float qa[4] = {qv.x, qv.y, qv.z, qv.w};
            float ka[4] = {kv.x, kv.y, kv.z, kv.w};
            #pragma unroll
            for (int qi = 0; qi < 4; qi++)
                #pragma unroll
                for (int jj = 0; jj < 4; jj++)
                    s[qi][jj] += qa[qi] * ka[jj];
        }

        // scale, mask, stage to Ps[j][q]
        #pragma unroll
        for (int qi = 0; qi < 4; qi++) {
            #pragma unroll
            for (int jj = 0; jj < 4; jj++) {
                float val = s[qi][jj] * 0.125f;   // 1/sqrt(64)
                if (CAUSAL && t == (int)blockIdx.x) {
                    if (j0 + tx * 4 + jj > q0 + ty * 4 + qi) val = -1e9f;
                }
                Ps[(tx * 4 + jj) * ATT_LD + ty * 4 + qi] = val;
            }
        }
        __syncthreads();

        // Online softmax: 4 threads per query row
        {
            int qq = tid >> 2, part = tid & 3;
            float pm = -INFINITY;
            #pragma unroll
            for (int i = 0; i < 16; i++)
                pm = fmaxf(pm, Ps[(part * 16 + i) * ATT_LD + qq]);
            pm = fmaxf(pm, __shfl_xor_sync(0xffffffffu, pm, 1));
            pm = fmaxf(pm, __shfl_xor_sync(0xffffffffu, pm, 2));
            float m_old = mrow[qq];
            float m_new = fmaxf(m_old, pm);
            float psum = 0.f;
            #pragma unroll
            for (int i = 0; i < 16; i++) {
                float* p = &Ps[(part * 16 + i) * ATT_LD + qq];
                float e = __expf(*p - m_new);
                *p = e;
                psum += e;
            }
            psum += __shfl_xor_sync(0xffffffffu, psum, 1);
            psum += __shfl_xor_sync(0xffffffffu, psum, 2);
            if (part == 0) {
                float al = __expf(m_old - m_new);
                arow[qq] = al;
                lrow[qq] = lrow[qq] * al + psum;
                mrow[qq] = m_new;
            }
        }
        __syncthreads();

        // Rescale accumulators, load V tile [j][d] into KV buffer
        {
            float a0 = arow[ty * 4 + 0], a1 = arow[ty * 4 + 1];
            float a2 = arow[ty * 4 + 2], a3 = arow[ty * 4 + 3];
            #pragma unroll
            for (int j = 0; j < 4; j++) {
                o[0][j] *= a0; o[1][j] *= a1; o[2][j] *= a2; o[3][j] *= a3;
            }
        }
        for (int idx = tid; idx < 64 * 64; idx += 256) {
            int jj = idx >> 6, d = idx & 63;
            KVs[jj * ATT_LD + d] = V[bk + (size_t)(j0 + jj) * DMODEL + d];
        }
        __syncthreads();

        // O += P @ V
        #pragma unroll 8
        for (int j = 0; j < 64; j++) {
            float4 pv = *(const float4*)(Ps + j * ATT_LD + ty * 4);
            float4 vv = *(const float4*)(KVs + j * ATT_LD + tx * 4);
            float pa[4] = {pv.x, pv.y, pv.z, pv.w};
            float va[4] = {vv.x, vv.y, vv.z, vv.w};
            #pragma unroll
            for (int qi = 0; qi < 4; qi++)
                #pragma unroll
                for (int dd = 0; dd < 4; dd++)
                    o[qi][dd] += pa[qi] * va[dd];
        }
        __syncthreads();
    }

    // Epilogue: divide by l, write out
    #pragma unroll
    for (int qi = 0; qi < 4; qi++) {
        float inv = 1.0f / lrow[ty * 4 + qi];
        size_t oidx = bq + (size_t)(ty * 4 + qi) * DMODEL + tx * 4;
        float4 ov = make_float4(o[qi][0] * inv, o[qi][1] * inv,
                                o[qi][2] * inv, o[qi][3] * inv);
        *(float4*)(O + oidx) = ov;
    }
}

#define SMEM_ATTN ((3 * 64 * ATT_LD + 3 * 64) * (int)sizeof(float))

// ---------------------------------------------------------------------------
// Orchestration
// ---------------------------------------------------------------------------
extern "C" void kernel_launch(void* const* d_in, const int* in_sizes, int n_in,
                              void* d_out, int out_size)
{
    const float* x     = (const float*)d_in[0];
    const float* enc   = (const float*)d_in[1];
    // d_in[2] src_mask: all ones; d_in[3] tgt_mask: causal -> handled in-kernel
    const float* sa_wq = (const float*)d_in[4];
    const float* sa_wk = (const float*)d_in[5];
    const float* sa_wv = (const float*)d_in[6];
    const float* sa_wo = (const float*)d_in[7];
    const float* sa_bo = (const float*)d_in[8];
    const float* ca_wq = (const float*)d_in[9];
    const float* ca_wk = (const float*)d_in[10];
    const float* ca_wv = (const float*)d_in[11];
    const float* ca_wo = (const float*)d_in[12];
    const float* ca_bo = (const float*)d_in[13];
    const float* ff_w1 = (const float*)d_in[14];
    const float* ff_b1 = (const float*)d_in[15];
    const float* ff_w2 = (const float*)d_in[16];
    const float* ff_b2 = (const float*)d_in[17];
    const float* ln0_g = (const float*)d_in[18];
    const float* ln0_b = (const float*)d_in[19];
    const float* ln1_g = (const float*)d_in[20];
    const float* ln1_b = (const float*)d_in[21];
    const float* ln2_g = (const float*)d_in[22];
    const float* ln2_b = (const float*)d_in[23];
    float* out = (float*)d_out;

    float *h, *q, *k, *v, *att, *x1, *x2, *ff;
    cudaGetSymbolAddress((void**)&h,   g_h);
    cudaGetSymbolAddress((void**)&q,   g_q);
    cudaGetSymbolAddress((void**)&k,   g_k);
    cudaGetSymbolAddress((void**)&v,   g_v);
    cudaGetSymbolAddress((void**)&att, g_att);
    cudaGetSymbolAddress((void**)&x1,  g_x1);
    cudaGetSymbolAddress((void**)&x2,  g_x2);
    cudaGetSymbolAddress((void**)&ff,  g_ff);

    cudaFuncSetAttribute(attn_kernel<true>,
                         cudaFuncAttributeMaxDynamicSharedMemorySize, SMEM_ATTN);
    cudaFuncSetAttribute(attn_kernel<false>,
                         cudaFuncAttributeMaxDynamicSharedMemorySize, SMEM_ATTN);

    dim3 gproj(DMODEL / 64, MROWS / 128);   // (8, 64)
    dim3 gff1(DFF / 64, MROWS / 128);       // (32, 64)
    dim3 gattn(SEQ / 64, NHEAD, BATCH);     // (32, 8, 4)

    // --- Self-attention block ---
    ln_kernel<<<MROWS, 128>>>(x, ln0_g, ln0_b, h);
    gemm_kernel<false, false, false><<<gproj, 256>>>(h, sa_wq, nullptr, nullptr, q, MROWS, DMODEL, DMODEL);
    gemm_kernel<false, false, false><<<gproj, 256>>>(h, sa_wk, nullptr, nullptr, k, MROWS, DMODEL, DMODEL);
    gemm_kernel<false, false, false><<<gproj, 256>>>(h, sa_wv, nullptr, nullptr, v, MROWS, DMODEL, DMODEL);
    attn_kernel<true><<<gattn, 256, SMEM_ATTN>>>(q, k, v, att);
    gemm_kernel<true, true, false><<<gproj, 256>>>(att, sa_wo, sa_bo, x, x1, MROWS, DMODEL, DMODEL);

    // --- Cross-attention block ---
    ln_kernel<<<MROWS, 128>>>(x1, ln1_g, ln1_b, h);
    gemm_kernel<false, false, false><<<gproj, 256>>>(h,   ca_wq, nullptr, nullptr, q, MROWS, DMODEL, DMODEL);
    gemm_kernel<false, false, false><<<gproj, 256>>>(enc, ca_wk, nullptr, nullptr, k, MROWS, DMODEL, DMODEL);
    gemm_kernel<false, false, false><<<gproj, 256>>>(enc, ca_wv, nullptr, nullptr, v, MROWS, DMODEL, DMODEL);
    attn_kernel<false><<<gattn, 256, SMEM_ATTN>>>(q, k, v, att);
    gemm_kernel<true, true, false><<<gproj, 256>>>(att, ca_wo, ca_bo, x1, x2, MROWS, DMODEL, DMODEL);

    // --- Feed-forward block ---
    ln_kernel<<<MROWS, 128>>>(x2, ln2_g, ln2_b, h);
    gemm_kernel<true, false, true><<<gff1, 256>>>(h, ff_w1, ff_b1, nullptr, ff, MROWS, DFF, DMODEL);
    gemm_kernel<true, true, false><<<gproj, 256>>>(ff, ff_w2, ff_b2, x2, out, MROWS, DMODEL, DFF);
}

// round 3
// speedup vs baseline: 1.3824x; 1.3824x over previous
#include <cuda_runtime.h>
#include <cuda_bf16.h>
#include <cstdint>
#include <math.h>

// Problem constants
#define BATCH 4
#define SEQ   2048
#define DMODEL 512
#define NHEAD 8
#define DHEAD 64
#define DFF   2048
#define MROWS (BATCH * SEQ)   // 8192

// ---------------------------------------------------------------------------
// Scratch (allocation-free: __device__ globals)
// ---------------------------------------------------------------------------
__device__ float g_h  [(size_t)MROWS * DMODEL];
__device__ float g_q  [(size_t)MROWS * DMODEL];
__device__ float g_k  [(size_t)MROWS * DMODEL];
__device__ float g_v  [(size_t)MROWS * DMODEL];
__device__ float g_att[(size_t)MROWS * DMODEL];
__device__ float g_x1 [(size_t)MROWS * DMODEL];
__device__ float g_x2 [(size_t)MROWS * DMODEL];
__device__ float g_ff [(size_t)MROWS * DFF];

// ---------------------------------------------------------------------------
// Warp MMA helpers (compute_103-safe: mma.sync + ldmatrix, no 'a' features)
// ---------------------------------------------------------------------------
__device__ __forceinline__ uint32_t smem_u32(const void* p) {
    uint32_t a;
    asm("{ .reg .u64 t; cvta.to.shared.u64 t, %1; cvt.u32.u64 %0, t; }"
        : "=r"(a) : "l"(p));
    return a;
}

__device__ __forceinline__ void ldm_x4(uint32_t* r, const void* p) {
    uint32_t a = smem_u32(p);
    asm volatile("ldmatrix.sync.aligned.m8n8.x4.shared.b16 {%0,%1,%2,%3}, [%4];"
        : "=r"(r[0]), "=r"(r[1]), "=r"(r[2]), "=r"(r[3]) : "r"(a));
}

// D += A(16x16,row) * B(16x8,col)  bf16 in, fp32 acc
__device__ __forceinline__ void mma_bf16(float* d, const uint32_t* a,
                                         uint32_t b0, uint32_t b1) {
    asm volatile(
        "mma.sync.aligned.m16n8k16.row.col.f32.bf16.bf16.f32 "
        "{%0,%1,%2,%3}, {%4,%5,%6,%7}, {%8,%9}, {%0,%1,%2,%3};"
        : "+f"(d[0]), "+f"(d[1]), "+f"(d[2]), "+f"(d[3])
        : "r"(a[0]), "r"(a[1]), "r"(a[2]), "r"(a[3]), "r"(b0), "r"(b1));
}

// fp32 -> (hi, lo) bf16 split, packed as bf16x2
__device__ __forceinline__ void cvt_split4(float4 a, uint2& hi, uint2& lo) {
    uint32_t h[4], l[4];
    float f[4] = {a.x, a.y, a.z, a.w};
    #pragma unroll
    for (int i = 0; i < 4; i++) {
        __nv_bfloat16 bh = __float2bfloat16_rn(f[i]);
        float r = f[i] - __bfloat162float(bh);
        __nv_bfloat16 bl = __float2bfloat16_rn(r);
        h[i] = (uint32_t)__bfloat16_as_ushort(bh);
        l[i] = (uint32_t)__bfloat16_as_ushort(bl);
    }
    hi.x = h[0] | (h[1] << 16); hi.y = h[2] | (h[3] << 16);
    lo.x = l[0] | (l[1] << 16); lo.y = l[2] | (l[3] << 16);
}

// ---------------------------------------------------------------------------
// LayerNorm (unchanged — proven)
// ---------------------------------------------------------------------------
__global__ void ln_kernel(const float* __restrict__ x,
                          const float* __restrict__ g,
                          const float* __restrict__ b,
                          float* __restrict__ out)
{
    int row = blockIdx.x;
    int t = threadIdx.x;  // 0..127
    const float4 v = ((const float4*)(x + (size_t)row * DMODEL))[t];

    __shared__ float red1[4], red2[4];

    float s = v.x + v.y + v.z + v.w;
    #pragma unroll
    for (int o = 16; o; o >>= 1) s += __shfl_xor_sync(0xffffffffu, s, o);
    if ((t & 31) == 0) red1[t >> 5] = s;
    __syncthreads();
    float mean = (red1[0] + red1[1] + red1[2] + red1[3]) * (1.0f / DMODEL);

    float d0 = v.x - mean, d1 = v.y - mean, d2 = v.z - mean, d3 = v.w - mean;
    float sq = d0*d0 + d1*d1 + d2*d2 + d3*d3;
    #pragma unroll
    for (int o = 16; o; o >>= 1) sq += __shfl_xor_sync(0xffffffffu, sq, o);
    if ((t & 31) == 0) red2[t >> 5] = sq;
    __syncthreads();
    float var = (red2[0] + red2[1] + red2[2] + red2[3]) * (1.0f / (DMODEL - 1));
    float rstd = 1.0f / (sqrtf(var) + 1e-6f);

    const float4 gv = ((const float4*)g)[t];
    const float4 bv = ((const float4*)b)[t];
    float4 o4;
    o4.x = gv.x * d0 * rstd + bv.x;
    o4.y = gv.y * d1 * rstd + bv.y;
    o4.z = gv.z * d2 * rstd + bv.z;
    o4.w = gv.w * d3 * rstd + bv.w;
    ((float4*)(out + (size_t)row * DMODEL))[t] = o4;
}

// ---------------------------------------------------------------------------
// HMMA GEMM: C[M,N] = A[M,K] @ W[K,N] (+bias)(+res)(+relu), 3x-bf16 split.
// Tile 128x128, BK=32, 256 threads = 8 warps (4M x 2N), warp = 32M x 64N.
// Smem rows padded to 40 bf16 (80B) -> conflict-free ldmatrix groups.
// ---------------------------------------------------------------------------
#define LDA 40

template<bool BIAS, bool RES, bool RELU>
__global__ void __launch_bounds__(256, 2)
gemm_mma(const float* __restrict__ A, const float* __restrict__ W,
         const float* __restrict__ bias, const float* __restrict__ res,
         float* __restrict__ C, int M, int N, int K)
{
    __shared__ __align__(16) uint16_t Ah[128 * LDA], Al[128 * LDA];
    __shared__ __align__(16) uint16_t Bh[128 * LDA], Bl[128 * LDA];

    const int tid  = threadIdx.x;
    const int lane = tid & 31;
    const int wid  = tid >> 5;
    const int m0 = blockIdx.y * 128;
    const int n0 = blockIdx.x * 128;
    const int wm = (wid >> 1) * 32;     // warp m-base within tile
    const int wn = (wid & 1) * 64;      // warp n-base within tile

    float acc[2][8][4];
    #pragma unroll
    for (int i = 0; i < 2; i++)
        #pragma unroll
        for (int j = 0; j < 8; j++)
            #pragma unroll
            for (int c = 0; c < 4; c++) acc[i][j][c] = 0.f;

    for (int k0 = 0; k0 < K; k0 += 32) {
        // ---- A tile: 128 rows x 32 k (fp32) -> split bf16 smem ----
        #pragma unroll
        for (int it = 0; it < 4; it++) {
            int row = (tid >> 3) + it * 32;
            int kv  = tid & 7;            // float4 index within row
            float4 a = *(const float4*)(A + (size_t)(m0 + row) * K + k0 + kv * 4);
            uint2 hi, lo; cvt_split4(a, hi, lo);
            *(uint2*)(Ah + row * LDA + kv * 4) = hi;
            *(uint2*)(Al + row * LDA + kv * 4) = lo;
        }
        // ---- B tile: W[K,N] -> Bs[n][k] (transposed), split bf16 ----
        #pragma unroll
        for (int it = 0; it < 4; it++) {
            int tsk = tid + it * 256;
            int n = tsk & 127, kg = tsk >> 7;   // kg: 0..7, 4 k each
            const float* wp = W + (size_t)(k0 + kg * 4) * N + n0 + n;
            float4 w;
            w.x = wp[0]; w.y = wp[(size_t)N]; w.z = wp[(size_t)2 * N]; w.w = wp[(size_t)3 * N];
            uint2 hi, lo; cvt_split4(w, hi, lo);
            *(uint2*)(Bh + n * LDA + kg * 4) = hi;
            *(uint2*)(Bl + n * LDA + kg * 4) = lo;
        }
        __syncthreads();

        #pragma unroll
        for (int ks = 0; ks < 32; ks += 16) {
            uint32_t ah[2][4], al[2][4];
            #pragma unroll
            for (int mi = 0; mi < 2; mi++) {
                const uint16_t* pa = Ah + (wm + mi * 16 + (lane & 15)) * LDA
                                   + ks + (lane >> 4) * 8;
                const uint16_t* pl = Al + (wm + mi * 16 + (lane & 15)) * LDA
                                   + ks + (lane >> 4) * 8;
                ldm_x4(ah[mi], pa);
                ldm_x4(al[mi], pl);
            }
            #pragma unroll
            for (int ni = 0; ni < 4; ni++) {
                uint32_t bh[4], bl[4];
                const uint16_t* pb = Bh + (wn + ni * 16 + (lane & 15)) * LDA
                                   + ks + (lane >> 4) * 8;
                const uint16_t* pbl = Bl + (wn + ni * 16 + (lane & 15)) * LDA
                                    + ks + (lane >> 4) * 8;
                ldm_x4(bh, pb);
                ldm_x4(bl, pbl);
                #pragma unroll
                for (int mi = 0; mi < 2; mi++) {
                    float* d0 = acc[mi][ni * 2];
                    float* d1 = acc[mi][ni * 2 + 1];
                    // n-cols 0-7 of this 16n group: b = {r0, r2}
                    mma_bf16(d0, ah[mi], bh[0], bh[2]);
                    mma_bf16(d0, ah[mi], bl[0], bl[2]);
                    mma_bf16(d0, al[mi], bh[0], bh[2]);
                    // n-cols 8-15: b = {r1, r3}
                    mma_bf16(d1, ah[mi], bh[1], bh[3]);
                    mma_bf16(d1, ah[mi], bl[1], bl[3]);
                    mma_bf16(d1, al[mi], bh[1], bh[3]);
                }
            }
        }
        __syncthreads();
    }

    // ---- Epilogue: frag (row = lane/4 (+8), col = lane%4*2) ----
    const int er = lane >> 2;
    const int ec = (lane & 3) * 2;
    #pragma unroll
    for (int mi = 0; mi < 2; mi++) {
        #pragma unroll
        for (int nf = 0; nf < 8; nf++) {
            int gm0 = m0 + wm + mi * 16 + er;
            int gn  = n0 + wn + nf * 8 + ec;
            #pragma unroll
            for (int half = 0; half < 2; half++) {
                int gm = gm0 + half * 8;
                float2 cv = make_float2(acc[mi][nf][half * 2],
                                        acc[mi][nf][half * 2 + 1]);
                if (BIAS) {
                    cv.x += bias[gn]; cv.y += bias[gn + 1];
                }
                if (RES) {
                    const float2 rv = *(const float2*)(res + (size_t)gm * N + gn);
                    cv.x += rv.x; cv.y += rv.y;
                }
                if (RELU) {
                    cv.x = fmaxf(cv.x, 0.f); cv.y = fmaxf(cv.y, 0.f);
                }
                *(float2*)(C + (size_t)gm * N + gn) = cv;
            }
        }
    }
}

// ---------------------------------------------------------------------------
// Fused attention (flash style), fp32 — unchanged (proven)
// ---------------------------------------------------------------------------
#define ATT_LD 68

template<bool CAUSAL>
__global__ void __launch_bounds__(256)
attn_kernel(const float* __restrict__ Q, const float* __restrict__ K,
            const float* __restrict__ V, float* __restrict__ O)
{
    extern __shared__ float sm[];
    float* Qs  = sm;
    float* KVs = Qs + 64 * ATT_LD;
    float* Ps  = KVs + 64 * ATT_LD;
    float* mrow = Ps + 64 * ATT_LD;
    float* lrow = mrow + 64;
    float* arow = lrow + 64;

    const int tid = threadIdx.x;
    const int tx = tid & 15;
    const int ty = tid >> 4;
    const int q0 = blockIdx.x * 64;
    const int h  = blockIdx.y;
    const int b  = blockIdx.z;

    const size_t bq = ((size_t)b * SEQ + q0) * DMODEL + (size_t)h * DHEAD;
    const size_t bk = ((size_t)b * SEQ) * DMODEL + (size_t)h * DHEAD;

    if (tid < 64) { mrow[tid] = -INFINITY; lrow[tid] = 0.f; }

    for (int idx = tid; idx < 64 * 64; idx += 256) {
        int qq = idx >> 6, d = idx & 63;
        Qs[d * ATT_LD + qq] = Q[bq + (size_t)qq * DMODEL + d];
    }

    float o[4][4];
    #pragma unroll
    for (int i = 0; i < 4; i++)
        #pragma unroll
        for (int j = 0; j < 4; j++) o[i][j] = 0.f;

    const int ntiles = CAUSAL ? (blockIdx.x + 1) : (SEQ / 64);

    for (int t = 0; t < ntiles; t++) {
        const int j0 = t * 64;
        for (int idx = tid; idx < 64 * 64; idx += 256) {
            int jj = idx >> 6, d = idx & 63;
            KVs[d * ATT_LD + jj] = K[bk + (size_t)(j0 + jj) * DMODEL + d];
        }
        __syncthreads();

        float s[4][4];
        #pragma unroll
        for (int i = 0; i < 4; i++)
            #pragma unroll
            for (int j = 0; j < 4; j++) s[i][j] = 0.f;

        #pragma unroll 8
        for (int d = 0; d < 64; d++) {
            float4 qv = *(const float4*)(Qs + d * ATT_LD + ty * 4);
            float4 kv = *(const float4*)(KVs + d * ATT_LD + tx * 4);
            float qa[4] = {qv.x, qv.y, qv.z, qv.w};
            float ka[4] = {kv.x, kv.y, kv.z, kv.w};
            #pragma unroll
            for (int qi = 0; qi < 4; qi++)
                #pragma unroll
                for (int jj = 0; jj < 4; jj++)
                    s[qi][jj] += qa[qi] * ka[jj];
        }

        #pragma unroll
        for (int qi = 0; qi < 4; qi++) {
            #pragma unroll
            for (int jj = 0; jj < 4; jj++) {
                float val = s[qi][jj] * 0.125f;
                if (CAUSAL && t == (int)blockIdx.x) {
                    if (j0 + tx * 4 + jj > q0 + ty * 4 + qi) val = -1e9f;
                }
                Ps[(tx * 4 + jj) * ATT_LD + ty * 4 + qi] = val;
            }
        }
        __syncthreads();

        {
            int qq = tid >> 2, part = tid & 3;
            float pm = -INFINITY;
            #pragma unroll
            for (int i = 0; i < 16; i++)
                pm = fmaxf(pm, Ps[(part * 16 + i) * ATT_LD + qq]);
            pm = fmaxf(pm, __shfl_xor_sync(0xffffffffu, pm, 1));
            pm = fmaxf(pm, __shfl_xor_sync(0xffffffffu, pm, 2));
            float m_old = mrow[qq];
            float m_new = fmaxf(m_old, pm);
            float psum = 0.f;
            #pragma unroll
            for (int i = 0; i < 16; i++) {
                float* p = &Ps[(part * 16 + i) * ATT_LD + qq];
                float e = __expf(*p - m_new);
                *p = e;
                psum += e;
            }
            psum += __shfl_xor_sync(0xffffffffu, psum, 1);
            psum += __shfl_xor_sync(0xffffffffu, psum, 2);
            if (part == 0) {
                float al = __expf(m_old - m_new);
                arow[qq] = al;
                lrow[qq] = lrow[qq] * al + psum;
                mrow[qq] = m_new;
            }
        }
        __syncthreads();

        {
            float a0 = arow[ty * 4 + 0], a1 = arow[ty * 4 + 1];
            float a2 = arow[ty * 4 + 2], a3 = arow[ty * 4 + 3];
            #pragma unroll
            for (int j = 0; j < 4; j++) {
                o[0][j] *= a0; o[1][j] *= a1; o[2][j] *= a2; o[3][j] *= a3;
            }
        }
        for (int idx = tid; idx < 64 * 64; idx += 256) {
            int jj = idx >> 6, d = idx & 63;
            KVs[jj * ATT_LD + d] = V[bk + (size_t)(j0 + jj) * DMODEL + d];
        }
        __syncthreads();

        #pragma unroll 8
        for (int j = 0; j < 64; j++) {
            float4 pv = *(const float4*)(Ps + j * ATT_LD + ty * 4);
            float4 vv = *(const float4*)(KVs + j * ATT_LD + tx * 4);
            float pa[4] = {pv.x, pv.y, pv.z, pv.w};
            float va[4] = {vv.x, vv.y, vv.z, vv.w};
            #pragma unroll
            for (int qi = 0; qi < 4; qi++)
                #pragma unroll
                for (int dd = 0; dd < 4; dd++)
                    o[qi][dd] += pa[qi] * va[dd];
        }
        __syncthreads();
    }

    #pragma unroll
    for (int qi = 0; qi < 4; qi++) {
        float inv = 1.0f / lrow[ty * 4 + qi];
        size_t oidx = bq + (size_t)(ty * 4 + qi) * DMODEL + tx * 4;
        float4 ov = make_float4(o[qi][0] * inv, o[qi][1] * inv,
                                o[qi][2] * inv, o[qi][3] * inv);
        *(float4*)(O + oidx) = ov;
    }
}

#define SMEM_ATTN ((3 * 64 * ATT_LD + 3 * 64) * (int)sizeof(float))

// ---------------------------------------------------------------------------
// Orchestration
// ---------------------------------------------------------------------------
extern "C" void kernel_launch(void* const* d_in, const int* in_sizes, int n_in,
                              void* d_out, int out_size)
{
    const float* x     = (const float*)d_in[0];
    const float* enc   = (const float*)d_in[1];
    const float* sa_wq = (const float*)d_in[4];
    const float* sa_wk = (const float*)d_in[5];
    const float* sa_wv = (const float*)d_in[6];
    const float* sa_wo = (const float*)d_in[7];
    const float* sa_bo = (const float*)d_in[8];
    const float* ca_wq = (const float*)d_in[9];
    const float* ca_wk = (const float*)d_in[10];
    const float* ca_wv = (const float*)d_in[11];
    const float* ca_wo = (const float*)d_in[12];
    const float* ca_bo = (const float*)d_in[13];
    const float* ff_w1 = (const float*)d_in[14];
    const float* ff_b1 = (const float*)d_in[15];
    const float* ff_w2 = (const float*)d_in[16];
    const float* ff_b2 = (const float*)d_in[17];
    const float* ln0_g = (const float*)d_in[18];
    const float* ln0_b = (const float*)d_in[19];
    const float* ln1_g = (const float*)d_in[20];
    const float* ln1_b = (const float*)d_in[21];
    const float* ln2_g = (const float*)d_in[22];
    const float* ln2_b = (const float*)d_in[23];
    float* out = (float*)d_out;

    float *h, *q, *k, *v, *att, *x1, *x2, *ff;
    cudaGetSymbolAddress((void**)&h,   g_h);
    cudaGetSymbolAddress((void**)&q,   g_q);
    cudaGetSymbolAddress((void**)&k,   g_k);
    cudaGetSymbolAddress((void**)&v,   g_v);
    cudaGetSymbolAddress((void**)&att, g_att);
    cudaGetSymbolAddress((void**)&x1,  g_x1);
    cudaGetSymbolAddress((void**)&x2,  g_x2);
    cudaGetSymbolAddress((void**)&ff,  g_ff);

    cudaFuncSetAttribute(attn_kernel<true>,
                         cudaFuncAttributeMaxDynamicSharedMemorySize, SMEM_ATTN);
    cudaFuncSetAttribute(attn_kernel<false>,
                         cudaFuncAttributeMaxDynamicSharedMemorySize, SMEM_ATTN);

    dim3 gproj(DMODEL / 128, MROWS / 128);  // (4, 64)
    dim3 gff1(DFF / 128, MROWS / 128);      // (16, 64)
    dim3 gattn(SEQ / 64, NHEAD, BATCH);     // (32, 8, 4)

    // --- Self-attention block ---
    ln_kernel<<<MROWS, 128>>>(x, ln0_g, ln0_b, h);
    gemm_mma<false, false, false><<<gproj, 256>>>(h, sa_wq, nullptr, nullptr, q, MROWS, DMODEL, DMODEL);
    gemm_mma<false, false, false><<<gproj, 256>>>(h, sa_wk, nullptr, nullptr, k, MROWS, DMODEL, DMODEL);
    gemm_mma<false, false, false><<<gproj, 256>>>(h, sa_wv, nullptr, nullptr, v, MROWS, DMODEL, DMODEL);
    attn_kernel<true><<<gattn, 256, SMEM_ATTN>>>(q, k, v, att);
    gemm_mma<true, true, false><<<gproj, 256>>>(att, sa_wo, sa_bo, x, x1, MROWS, DMODEL, DMODEL);

    // --- Cross-attention block ---
    ln_kernel<<<MROWS, 128>>>(x1, ln1_g, ln1_b, h);
    gemm_mma<false, false, false><<<gproj, 256>>>(h,   ca_wq, nullptr, nullptr, q, MROWS, DMODEL, DMODEL);
    gemm_mma<false, false, false><<<gproj, 256>>>(enc, ca_wk, nullptr, nullptr, k, MROWS, DMODEL, DMODEL);
    gemm_mma<false, false, false><<<gproj, 256>>>(enc, ca_wv, nullptr, nullptr, v, MROWS, DMODEL, DMODEL);
    attn_kernel<false><<<gattn, 256, SMEM_ATTN>>>(q, k, v, att);
    gemm_mma<true, true, false><<<gproj, 256>>>(att, ca_wo, ca_bo, x1, x2, MROWS, DMODEL, DMODEL);

    // --- Feed-forward block ---
    ln_kernel<<<MROWS, 128>>>(x2, ln2_g, ln2_b, h);
    gemm_mma<true, false, true><<<gff1, 256>>>(h, ff_w1, ff_b1, nullptr, ff, MROWS, DFF, DMODEL);
    gemm_mma<true, true, false><<<gproj, 256>>>(ff, ff_w2, ff_b2, x2, out, MROWS, DMODEL, DFF);
}

// round 4
// speedup vs baseline: 2.6593x; 1.9236x over previous
#include <cuda_runtime.h>
#include <cuda_bf16.h>
#include <cstdint>
#include <math.h>

// Problem constants
#define BATCH 4
#define SEQ   2048
#define DMODEL 512
#define NHEAD 8
#define DHEAD 64
#define DFF   2048
#define MROWS (BATCH * SEQ)   // 8192

// ---------------------------------------------------------------------------
// Scratch (allocation-free: __device__ globals)
// ---------------------------------------------------------------------------
__device__ float g_h  [(size_t)MROWS * DMODEL];
__device__ float g_q  [(size_t)MROWS * DMODEL];
__device__ float g_k  [(size_t)MROWS * DMODEL];
__device__ float g_v  [(size_t)MROWS * DMODEL];
__device__ float g_att[(size_t)MROWS * DMODEL];
__device__ float g_x1 [(size_t)MROWS * DMODEL];
__device__ float g_x2 [(size_t)MROWS * DMODEL];
__device__ float g_ff [(size_t)MROWS * DFF];

// ---------------------------------------------------------------------------
// Warp MMA helpers (compute_103-safe: mma.sync + ldmatrix)
// ---------------------------------------------------------------------------
__device__ __forceinline__ uint32_t smem_u32(const void* p) {
    uint32_t a;
    asm("{ .reg .u64 t; cvta.to.shared.u64 t, %1; cvt.u32.u64 %0, t; }"
        : "=r"(a) : "l"(p));
    return a;
}

__device__ __forceinline__ void ldm_x4(uint32_t* r, const void* p) {
    uint32_t a = smem_u32(p);
    asm volatile("ldmatrix.sync.aligned.m8n8.x4.shared.b16 {%0,%1,%2,%3}, [%4];"
        : "=r"(r[0]), "=r"(r[1]), "=r"(r[2]), "=r"(r[3]) : "r"(a));
}

// D += A(16x16,row) * B(16x8,col)  bf16 in, fp32 acc
__device__ __forceinline__ void mma_bf16(float* d, const uint32_t* a,
                                         uint32_t b0, uint32_t b1) {
    asm volatile(
        "mma.sync.aligned.m16n8k16.row.col.f32.bf16.bf16.f32 "
        "{%0,%1,%2,%3}, {%4,%5,%6,%7}, {%8,%9}, {%0,%1,%2,%3};"
        : "+f"(d[0]), "+f"(d[1]), "+f"(d[2]), "+f"(d[3])
        : "r"(a[0]), "r"(a[1]), "r"(a[2]), "r"(a[3]), "r"(b0), "r"(b1));
}

// fp32 -> (hi, lo) bf16 split, packed as bf16x2
__device__ __forceinline__ void cvt_split4(float4 a, uint2& hi, uint2& lo) {
    uint32_t h[4], l[4];
    float f[4] = {a.x, a.y, a.z, a.w};
    #pragma unroll
    for (int i = 0; i < 4; i++) {
        __nv_bfloat16 bh = __float2bfloat16_rn(f[i]);
        float r = f[i] - __bfloat162float(bh);
        __nv_bfloat16 bl = __float2bfloat16_rn(r);
        h[i] = (uint32_t)__bfloat16_as_ushort(bh);
        l[i] = (uint32_t)__bfloat16_as_ushort(bl);
    }
    hi.x = h[0] | (h[1] << 16); hi.y = h[2] | (h[3] << 16);
    lo.x = l[0] | (l[1] << 16); lo.y = l[2] | (l[3] << 16);
}

// fp32 -> bf16 (single), 4-wide pack
__device__ __forceinline__ uint2 cvt4_bf16(float4 a) {
    uint32_t h0 = (uint32_t)__bfloat16_as_ushort(__float2bfloat16_rn(a.x));
    uint32_t h1 = (uint32_t)__bfloat16_as_ushort(__float2bfloat16_rn(a.y));
    uint32_t h2 = (uint32_t)__bfloat16_as_ushort(__float2bfloat16_rn(a.z));
    uint32_t h3 = (uint32_t)__bfloat16_as_ushort(__float2bfloat16_rn(a.w));
    uint2 r; r.x = h0 | (h1 << 16); r.y = h2 | (h3 << 16);
    return r;
}

__device__ __forceinline__ uint32_t pack_bf16(float a, float b) {
    return (uint32_t)__bfloat16_as_ushort(__float2bfloat16_rn(a))
         | ((uint32_t)__bfloat16_as_ushort(__float2bfloat16_rn(b)) << 16);
}

// Fast exp on FMA/ALU pipes (no MUFU). ~2e-6 rel err, valid for x <= ~80.
__device__ __forceinline__ float fexp(float x) {
    x = fmaxf(x, -80.f);
    float t = fmaf(x, 1.442695041f, 12582912.f);   // round(x*log2e) via shift
    int   n = __float_as_int(t) - 0x4B400000;
    float i_f = t - 12582912.f;
    float f = fmaf(x, 1.442695041f, -i_f);          // frac in [-0.5, 0.5]
    float p = 0.0013333558f;
    p = fmaf(p, f, 0.0096181291f);
    p = fmaf(p, f, 0.0555041087f);
    p = fmaf(p, f, 0.2402265069f);
    p = fmaf(p, f, 0.6931471806f);
    p = fmaf(p, f, 1.0f);
    return __int_as_float(__float_as_int(p) + (n << 23));
}

// ---------------------------------------------------------------------------
// LayerNorm (unchanged — proven)
// ---------------------------------------------------------------------------
__global__ void ln_kernel(const float* __restrict__ x,
                          const float* __restrict__ g,
                          const float* __restrict__ b,
                          float* __restrict__ out)
{
    int row = blockIdx.x;
    int t = threadIdx.x;  // 0..127
    const float4 v = ((const float4*)(x + (size_t)row * DMODEL))[t];

    __shared__ float red1[4], red2[4];

    float s = v.x + v.y + v.z + v.w;
    #pragma unroll
    for (int o = 16; o; o >>= 1) s += __shfl_xor_sync(0xffffffffu, s, o);
    if ((t & 31) == 0) red1[t >> 5] = s;
    __syncthreads();
    float mean = (red1[0] + red1[1] + red1[2] + red1[3]) * (1.0f / DMODEL);

    float d0 = v.x - mean, d1 = v.y - mean, d2 = v.z - mean, d3 = v.w - mean;
    float sq = d0*d0 + d1*d1 + d2*d2 + d3*d3;
    #pragma unroll
    for (int o = 16; o; o >>= 1) sq += __shfl_xor_sync(0xffffffffu, sq, o);
    if ((t & 31) == 0) red2[t >> 5] = sq;
    __syncthreads();
    float var = (red2[0] + red2[1] + red2[2] + red2[3]) * (1.0f / (DMODEL - 1));
    float rstd = 1.0f / (sqrtf(var) + 1e-6f);

    const float4 gv = ((const float4*)g)[t];
    const float4 bv = ((const float4*)b)[t];
    float4 o4;
    o4.x = gv.x * d0 * rstd + bv.x;
    o4.y = gv.y * d1 * rstd + bv.y;
    o4.z = gv.z * d2 * rstd + bv.z;
    o4.w = gv.w * d3 * rstd + bv.w;
    ((float4*)(out + (size_t)row * DMODEL))[t] = o4;
}

// ---------------------------------------------------------------------------
// HMMA GEMM (unchanged from R3 — proven at rel_err 2.8e-6)
// ---------------------------------------------------------------------------
#define LDA 40

template<bool BIAS, bool RES, bool RELU>
__global__ void __launch_bounds__(256, 2)
gemm_mma(const float* __restrict__ A, const float* __restrict__ W,
         const float* __restrict__ bias, const float* __restrict__ res,
         float* __restrict__ C, int M, int N, int K)
{
    __shared__ __align__(16) uint16_t Ah[128 * LDA], Al[128 * LDA];
    __shared__ __align__(16) uint16_t Bh[128 * LDA], Bl[128 * LDA];

    const int tid  = threadIdx.x;
    const int lane = tid & 31;
    const int wid  = tid >> 5;
    const int m0 = blockIdx.y * 128;
    const int n0 = blockIdx.x * 128;
    const int wm = (wid >> 1) * 32;
    const int wn = (wid & 1) * 64;

    float acc[2][8][4];
    #pragma unroll
    for (int i = 0; i < 2; i++)
        #pragma unroll
        for (int j = 0; j < 8; j++)
            #pragma unroll
            for (int c = 0; c < 4; c++) acc[i][j][c] = 0.f;

    for (int k0 = 0; k0 < K; k0 += 32) {
        #pragma unroll
        for (int it = 0; it < 4; it++) {
            int row = (tid >> 3) + it * 32;
            int kv  = tid & 7;
            float4 a = *(const float4*)(A + (size_t)(m0 + row) * K + k0 + kv * 4);
            uint2 hi, lo; cvt_split4(a, hi, lo);
            *(uint2*)(Ah + row * LDA + kv * 4) = hi;
            *(uint2*)(Al + row * LDA + kv * 4) = lo;
        }
        #pragma unroll
        for (int it = 0; it < 4; it++) {
            int tsk = tid + it * 256;
            int n = tsk & 127, kg = tsk >> 7;
            const float* wp = W + (size_t)(k0 + kg * 4) * N + n0 + n;
            float4 w;
            w.x = wp[0]; w.y = wp[(size_t)N]; w.z = wp[(size_t)2 * N]; w.w = wp[(size_t)3 * N];
            uint2 hi, lo; cvt_split4(w, hi, lo);
            *(uint2*)(Bh + n * LDA + kg * 4) = hi;
            *(uint2*)(Bl + n * LDA + kg * 4) = lo;
        }
        __syncthreads();

        #pragma unroll
        for (int ks = 0; ks < 32; ks += 16) {
            uint32_t ah[2][4], al[2][4];
            #pragma unroll
            for (int mi = 0; mi < 2; mi++) {
                ldm_x4(ah[mi], Ah + (wm + mi * 16 + (lane & 15)) * LDA + ks + (lane >> 4) * 8);
                ldm_x4(al[mi], Al + (wm + mi * 16 + (lane & 15)) * LDA + ks + (lane >> 4) * 8);
            }
            #pragma unroll
            for (int ni = 0; ni < 4; ni++) {
                uint32_t bh[4], bl[4];
                ldm_x4(bh, Bh + (wn + ni * 16 + (lane & 15)) * LDA + ks + (lane >> 4) * 8);
                ldm_x4(bl, Bl + (wn + ni * 16 + (lane & 15)) * LDA + ks + (lane >> 4) * 8);
                #pragma unroll
                for (int mi = 0; mi < 2; mi++) {
                    float* d0 = acc[mi][ni * 2];
                    float* d1 = acc[mi][ni * 2 + 1];
                    mma_bf16(d0, ah[mi], bh[0], bh[2]);
                    mma_bf16(d0, ah[mi], bl[0], bl[2]);
                    mma_bf16(d0, al[mi], bh[0], bh[2]);
                    mma_bf16(d1, ah[mi], bh[1], bh[3]);
                    mma_bf16(d1, ah[mi], bl[1], bl[3]);
                    mma_bf16(d1, al[mi], bh[1], bh[3]);
                }
            }
        }
        __syncthreads();
    }

    const int er = lane >> 2;
    const int ec = (lane & 3) * 2;
    #pragma unroll
    for (int mi = 0; mi < 2; mi++) {
        #pragma unroll
        for (int nf = 0; nf < 8; nf++) {
            int gm0 = m0 + wm + mi * 16 + er;
            int gn  = n0 + wn + nf * 8 + ec;
            #pragma unroll
            for (int half = 0; half < 2; half++) {
                int gm = gm0 + half * 8;
                float2 cv = make_float2(acc[mi][nf][half * 2],
                                        acc[mi][nf][half * 2 + 1]);
                if (BIAS) { cv.x += bias[gn]; cv.y += bias[gn + 1]; }
                if (RES) {
                    const float2 rv = *(const float2*)(res + (size_t)gm * N + gn);
                    cv.x += rv.x; cv.y += rv.y;
                }
                if (RELU) { cv.x = fmaxf(cv.x, 0.f); cv.y = fmaxf(cv.y, 0.f); }
                *(float2*)(C + (size_t)gm * N + gn) = cv;
            }
        }
    }
}

// ---------------------------------------------------------------------------
// Flash attention v2: bf16 mma.sync + poly-exp softmax.
// Block = 128 queries (1 head, 1 batch), 8 warps, key tiles of 128.
// smem layout (bytes from base):
//   Qs  [128][72]  bf16   @ 0       (18432)
//   Ks  [128][72]  bf16   @ 18432   (18432)
//   Vt  [64][136]  bf16   @ 36864   (17408)   V transposed: [d][j]
//   Ps  [128][136] bf16   @ 54272   (34816)
//   part_max [8][32] f32  @ 89088   (1024)
//   part_sum [8][32] f32  @ 90112   (1024)
//   mrow[128] f32         @ 91136
//   lrow[128] f32         @ 91648
//   arow[128] f32         @ 92160   total 92672
// ---------------------------------------------------------------------------
#define QLD 72
#define PLD 136
#define ATT2_SMEM 92672

template<bool CAUSAL>
__global__ void __launch_bounds__(256, 2)
attn_mma(const float* __restrict__ Q, const float* __restrict__ K,
         const float* __restrict__ V, float* __restrict__ O)
{
    extern __shared__ char asmem[];
    uint16_t* Qs = (uint16_t*)(asmem);
    uint16_t* Ks = (uint16_t*)(asmem + 18432);
    uint16_t* Vt = (uint16_t*)(asmem + 36864);
    uint16_t* Ps = (uint16_t*)(asmem + 54272);
    float* part_max = (float*)(asmem + 89088);   // [8][32]
    float* part_sum = (float*)(asmem + 90112);   // [8][32]
    float* mrow = (float*)(asmem + 91136);
    float* lrow = (float*)(asmem + 91648);
    float* arow = (float*)(asmem + 92160);

    const int tid  = threadIdx.x;
    const int lane = tid & 31;
    const int wid  = tid >> 5;
    const int wm   = (wid >> 1) * 32;     // q rows of this warp (both phases)
    const int wnk  = (wid & 1) * 64;      // key cols (phase 1)
    const int wnd  = (wid & 1) * 32;      // d cols (phase 2)
    const int er   = lane >> 2;
    const int ec   = (lane & 3) * 2;

    const int q0 = blockIdx.x * 128;
    const int h  = blockIdx.y;
    const int b  = blockIdx.z;

    const size_t bq = ((size_t)b * SEQ + q0) * DMODEL + (size_t)h * DHEAD;
    const size_t bk = ((size_t)b * SEQ) * DMODEL + (size_t)h * DHEAD;

    // Load Q tile [128][64] -> bf16
    #pragma unroll
    for (int it = 0; it < 8; it++) {
        int vI = tid + it * 256;
        int row = vI >> 4, c4 = vI & 15;
        float4 qv = *(const float4*)(Q + bq + (size_t)row * DMODEL + c4 * 4);
        *(uint2*)(Qs + row * QLD + c4 * 4) = cvt4_bf16(qv);
    }
    if (tid < 128) { mrow[tid] = -INFINITY; lrow[tid] = 0.f; }

    float o[2][4][4];
    #pragma unroll
    for (int mi = 0; mi < 2; mi++)
        #pragma unroll
        for (int nf = 0; nf < 4; nf++)
            #pragma unroll
            for (int c = 0; c < 4; c++) o[mi][nf][c] = 0.f;

    __syncthreads();

    const int ntiles = CAUSAL ? (blockIdx.x + 1) : (SEQ / 128);

    for (int t = 0; t < ntiles; t++) {
        const int j0 = t * 128;

        // ---- Load K tile [128 keys][64 d] -> bf16 ----
        #pragma unroll
        for (int it = 0; it < 8; it++) {
            int vI = tid + it * 256;
            int row = vI >> 4, c4 = vI & 15;
            float4 kv = *(const float4*)(K + bk + (size_t)(j0 + row) * DMODEL + c4 * 4);
            *(uint2*)(Ks + row * QLD + c4 * 4) = cvt4_bf16(kv);
        }
        __syncthreads();  // (A) K ready, prev PV done by all

        // ---- QK^T: warp computes 32q x 64k ----
        float sc[2][8][4];
        #pragma unroll
        for (int mi = 0; mi < 2; mi++)
            #pragma unroll
            for (int nf = 0; nf < 8; nf++)
                #pragma unroll
                for (int c = 0; c < 4; c++) sc[mi][nf][c] = 0.f;

        #pragma unroll
        for (int ks = 0; ks < 64; ks += 16) {
            uint32_t aq[2][4];
            #pragma unroll
            for (int mi = 0; mi < 2; mi++)
                ldm_x4(aq[mi], Qs + (wm + mi * 16 + (lane & 15)) * QLD + ks + (lane >> 4) * 8);
            #pragma unroll
            for (int ni = 0; ni < 4; ni++) {
                uint32_t bkf[4];
                ldm_x4(bkf, Ks + (wnk + ni * 16 + (lane & 15)) * QLD + ks + (lane >> 4) * 8);
                #pragma unroll
                for (int mi = 0; mi < 2; mi++) {
                    mma_bf16(sc[mi][ni * 2],     aq[mi], bkf[0], bkf[2]);
                    mma_bf16(sc[mi][ni * 2 + 1], aq[mi], bkf[1], bkf[3]);
                }
            }
        }

        // ---- Load V tile (transposed into Vt[d][j]) — overlaps with softmax ----
        #pragma unroll
        for (int it = 0; it < 8; it++) {
            int vI = tid + it * 256;
            int row = vI >> 4, c4 = vI & 15;
            float4 vv = *(const float4*)(V + bk + (size_t)(j0 + row) * DMODEL + c4 * 4);
            Vt[(c4 * 4 + 0) * PLD + row] = (uint16_t)__bfloat16_as_ushort(__float2bfloat16_rn(vv.x));
            Vt[(c4 * 4 + 1) * PLD + row] = (uint16_t)__bfloat16_as_ushort(__float2bfloat16_rn(vv.y));
            Vt[(c4 * 4 + 2) * PLD + row] = (uint16_t)__bfloat16_as_ushort(__float2bfloat16_rn(vv.z));
            Vt[(c4 * 4 + 3) * PLD + row] = (uint16_t)__bfloat16_as_ushort(__float2bfloat16_rn(vv.w));
        }

        // ---- scale + causal mask + per-thread row max ----
        float lm[2][2] = {{-INFINITY, -INFINITY}, {-INFINITY, -INFINITY}};
        #pragma unroll
        for (int mi = 0; mi < 2; mi++) {
            #pragma unroll
            for (int nf = 0; nf < 8; nf++) {
                #pragma unroll
                for (int c = 0; c < 4; c++) {
                    float val = sc[mi][nf][c] * 0.125f;
                    if (CAUSAL && t == (int)blockIdx.x) {
                        int gq = q0 + wm + mi * 16 + er + (c >> 1) * 8;
                        int gj = j0 + wnk + nf * 8 + ec + (c & 1);
                        if (gj > gq) val = -1e9f;
                    }
                    sc[mi][nf][c] = val;
                    lm[mi][c >> 1] = fmaxf(lm[mi][c >> 1], val);
                }
            }
        }
        #pragma unroll
        for (int mi = 0; mi < 2; mi++)
            #pragma unroll
            for (int hh = 0; hh < 2; hh++) {
                float v2 = lm[mi][hh];
                v2 = fmaxf(v2, __shfl_xor_sync(0xffffffffu, v2, 1));
                v2 = fmaxf(v2, __shfl_xor_sync(0xffffffffu, v2, 2));
                lm[mi][hh] = v2;
            }
        if ((lane & 3) == 0) {
            part_max[wid * 32 + 0 * 16 + 0 * 8 + er] = lm[0][0];
            part_max[wid * 32 + 0 * 16 + 1 * 8 + er] = lm[0][1];
            part_max[wid * 32 + 1 * 16 + 0 * 8 + er] = lm[1][0];
            part_max[wid * 32 + 1 * 16 + 1 * 8 + er] = lm[1][1];
        }
        __syncthreads();  // (B)

        // ---- combine max across warp pair; update m, alpha; fold alpha into l ----
        if (tid < 128) {
            int g = tid >> 5, rr = tid & 31;
            float pm = fmaxf(part_max[(2 * g) * 32 + rr], part_max[(2 * g + 1) * 32 + rr]);
            float mo = mrow[tid];
            float mn = fmaxf(mo, pm);
            float al = fexp(mo - mn);
            arow[tid] = al;
            mrow[tid] = mn;
            lrow[tid] *= al;
        }
        __syncthreads();  // (C)

        // ---- p = exp(s - m): write Ps (bf16), accumulate row sums ----
        float ls[2][2] = {{0.f, 0.f}, {0.f, 0.f}};
        #pragma unroll
        for (int mi = 0; mi < 2; mi++) {
            float m1 = mrow[wm + mi * 16 + er];
            float m2 = mrow[wm + mi * 16 + er + 8];
            #pragma unroll
            for (int nf = 0; nf < 8; nf++) {
                float p0 = fexp(sc[mi][nf][0] - m1);
                float p1 = fexp(sc[mi][nf][1] - m1);
                float p2 = fexp(sc[mi][nf][2] - m2);
                float p3 = fexp(sc[mi][nf][3] - m2);
                ls[mi][0] += p0 + p1;
                ls[mi][1] += p2 + p3;
                int col = wnk + nf * 8 + ec;
                *(uint32_t*)(Ps + (wm + mi * 16 + er) * PLD + col)     = pack_bf16(p0, p1);
                *(uint32_t*)(Ps + (wm + mi * 16 + er + 8) * PLD + col) = pack_bf16(p2, p3);
            }
        }
        #pragma unroll
        for (int mi = 0; mi < 2; mi++)
            #pragma unroll
            for (int hh = 0; hh < 2; hh++) {
                float v2 = ls[mi][hh];
                v2 += __shfl_xor_sync(0xffffffffu, v2, 1);
                v2 += __shfl_xor_sync(0xffffffffu, v2, 2);
                ls[mi][hh] = v2;
            }
        if ((lane & 3) == 0) {
            part_sum[wid * 32 + 0 * 16 + 0 * 8 + er] = ls[0][0];
            part_sum[wid * 32 + 0 * 16 + 1 * 8 + er] = ls[0][1];
            part_sum[wid * 32 + 1 * 16 + 0 * 8 + er] = ls[1][0];
            part_sum[wid * 32 + 1 * 16 + 1 * 8 + er] = ls[1][1];
        }

        // ---- rescale O accumulators by alpha (arow ready since (C)) ----
        #pragma unroll
        for (int mi = 0; mi < 2; mi++) {
            float a1 = arow[wm + mi * 16 + er];
            float a2 = arow[wm + mi * 16 + er + 8];
            #pragma unroll
            for (int nf = 0; nf < 4; nf++) {
                o[mi][nf][0] *= a1; o[mi][nf][1] *= a1;
                o[mi][nf][2] *= a2; o[mi][nf][3] *= a2;
            }
        }
        __syncthreads();  // (D) Ps, part_sum, Vt all visible

        if (tid < 128) {
            int g = tid >> 5, rr = tid & 31;
            lrow[tid] += part_sum[(2 * g) * 32 + rr] + part_sum[(2 * g + 1) * 32 + rr];
        }

        // ---- O += P @ V : warp computes 32q x 32d over 128 keys ----
        #pragma unroll
        for (int ks = 0; ks < 128; ks += 16) {
            uint32_t ap[2][4];
            #pragma unroll
            for (int mi = 0; mi < 2; mi++)
                ldm_x4(ap[mi], Ps + (wm + mi * 16 + (lane & 15)) * PLD + ks + (lane >> 4) * 8);
            #pragma unroll
            for (int ni = 0; ni < 2; ni++) {
                uint32_t bv[4];
                ldm_x4(bv, Vt + (wnd + ni * 16 + (lane & 15)) * PLD + ks + (lane >> 4) * 8);
                #pragma unroll
                for (int mi = 0; mi < 2; mi++) {
                    mma_bf16(o[mi][ni * 2],     ap[mi], bv[0], bv[2]);
                    mma_bf16(o[mi][ni * 2 + 1], ap[mi], bv[1], bv[3]);
                }
            }
        }
    }

    __syncthreads();  // lrow final

    // ---- epilogue: O / l ----
    #pragma unroll
    for (int mi = 0; mi < 2; mi++) {
        float inv1 = 1.0f / lrow[wm + mi * 16 + er];
        float inv2 = 1.0f / lrow[wm + mi * 16 + er + 8];
        #pragma unroll
        for (int nf = 0; nf < 4; nf++) {
            int gq1 = q0 + wm + mi * 16 + er;
            int col = h * DHEAD + wnd + nf * 8 + ec;
            size_t o1 = ((size_t)b * SEQ + gq1) * DMODEL + col;
            size_t o2 = ((size_t)b * SEQ + gq1 + 8) * DMODEL + col;
            *(float2*)(O + o1) = make_float2(o[mi][nf][0] * inv1, o[mi][nf][1] * inv1);
            *(float2*)(O + o2) = make_float2(o[mi][nf][2] * inv2, o[mi][nf][3] * inv2);
        }
    }
}

// ---------------------------------------------------------------------------
// Orchestration
// ---------------------------------------------------------------------------
extern "C" void kernel_launch(void* const* d_in, const int* in_sizes, int n_in,
                              void* d_out, int out_size)
{
    const float* x     = (const float*)d_in[0];
    const float* enc   = (const float*)d_in[1];
    const float* sa_wq = (const float*)d_in[4];
    const float* sa_wk = (const float*)d_in[5];
    const float* sa_wv = (const float*)d_in[6];
    const float* sa_wo = (const float*)d_in[7];
    const float* sa_bo = (const float*)d_in[8];
    const float* ca_wq = (const float*)d_in[9];
    const float* ca_wk = (const float*)d_in[10];
    const float* ca_wv = (const float*)d_in[11];
    const float* ca_wo = (const float*)d_in[12];
    const float* ca_bo = (const float*)d_in[13];
    const float* ff_w1 = (const float*)d_in[14];
    const float* ff_b1 = (const float*)d_in[15];
    const float* ff_w2 = (const float*)d_in[16];
    const float* ff_b2 = (const float*)d_in[17];
    const float* ln0_g = (const float*)d_in[18];
    const float* ln0_b = (const float*)d_in[19];
    const float* ln1_g = (const float*)d_in[20];
    const float* ln1_b = (const float*)d_in[21];
    const float* ln2_g = (const float*)d_in[22];
    const float* ln2_b = (const float*)d_in[23];
    float* out = (float*)d_out;

    float *h, *q, *k, *v, *att, *x1, *x2, *ff;
    cudaGetSymbolAddress((void**)&h,   g_h);
    cudaGetSymbolAddress((void**)&q,   g_q);
    cudaGetSymbolAddress((void**)&k,   g_k);
    cudaGetSymbolAddress((void**)&v,   g_v);
    cudaGetSymbolAddress((void**)&att, g_att);
    cudaGetSymbolAddress((void**)&x1,  g_x1);
    cudaGetSymbolAddress((void**)&x2,  g_x2);
    cudaGetSymbolAddress((void**)&ff,  g_ff);

    cudaFuncSetAttribute(attn_mma<true>,
                         cudaFuncAttributeMaxDynamicSharedMemorySize, ATT2_SMEM);
    cudaFuncSetAttribute(attn_mma<false>,
                         cudaFuncAttributeMaxDynamicSharedMemorySize, ATT2_SMEM);

    dim3 gproj(DMODEL / 128, MROWS / 128);  // (4, 64)
    dim3 gff1(DFF / 128, MROWS / 128);      // (16, 64)
    dim3 gattn(SEQ / 128, NHEAD, BATCH);    // (16, 8, 4)

    // --- Self-attention block ---
    ln_kernel<<<MROWS, 128>>>(x, ln0_g, ln0_b, h);
    gemm_mma<false, false, false><<<gproj, 256>>>(h, sa_wq, nullptr, nullptr, q, MROWS, DMODEL, DMODEL);
    gemm_mma<false, false, false><<<gproj, 256>>>(h, sa_wk, nullptr, nullptr, k, MROWS, DMODEL, DMODEL);
    gemm_mma<false, false, false><<<gproj, 256>>>(h, sa_wv, nullptr, nullptr, v, MROWS, DMODEL, DMODEL);
    attn_mma<true><<<gattn, 256, ATT2_SMEM>>>(q, k, v, att);
    gemm_mma<true, true, false><<<gproj, 256>>>(att, sa_wo, sa_bo, x, x1, MROWS, DMODEL, DMODEL);

    // --- Cross-attention block ---
    ln_kernel<<<MROWS, 128>>>(x1, ln1_g, ln1_b, h);
    gemm_mma<false, false, false><<<gproj, 256>>>(h,   ca_wq, nullptr, nullptr, q, MROWS, DMODEL, DMODEL);
    gemm_mma<false, false, false><<<gproj, 256>>>(enc, ca_wk, nullptr, nullptr, k, MROWS, DMODEL, DMODEL);
    gemm_mma<false, false, false><<<gproj, 256>>>(enc, ca_wv, nullptr, nullptr, v, MROWS, DMODEL, DMODEL);
    attn_mma<false><<<gattn, 256, ATT2_SMEM>>>(q, k, v, att);
    gemm_mma<true, true, false><<<gproj, 256>>>(att, ca_wo, ca_bo, x1, x2, MROWS, DMODEL, DMODEL);

    // --- Feed-forward block ---
    ln_kernel<<<MROWS, 128>>>(x2, ln2_g, ln2_b, h);
    gemm_mma<true, false, true><<<gff1, 256>>>(h, ff_w1, ff_b1, nullptr, ff, MROWS, DFF, DMODEL);
    gemm_mma<true, true, false><<<gproj, 256>>>(ff, ff_w2, ff_b2, x2, out, MROWS, DMODEL, DFF);
}